// round 14
// baseline (speedup 1.0000x reference)
#include <cuda_runtime.h>
#include <cuda_bf16.h>
#include <math.h>
#include <stdint.h>

typedef unsigned long long ull;

#define BS 32
#define NRR 100
#define IND 2048
#define QDIM 1024
#define CCH 256

__device__ float g_Qp[BS * CCH];
__device__ float g_Xp[BS * NRR * CCH];
__device__ float g_logits[2 * BS * NRR * NRR];
__device__ float g_bm[2 * BS];
__device__ float g_bsum[2 * BS];
__device__ __align__(16) unsigned short g_W1h[2 * 128 * 256];
__device__ __align__(16) unsigned short g_W1l[2 * 128 * 256];
__device__ __align__(16) unsigned short g_W2h[2 * 64 * 128];
__device__ __align__(16) unsigned short g_W2l[2 * 64 * 128];
__device__ __align__(16) unsigned short g_Wvh[256 * 2048];
__device__ __align__(16) unsigned short g_Wvl[256 * 2048];

__device__ __forceinline__ ull pack2(float x) {
    ull r; asm("mov.b64 %0, {%1,%1};" : "=l"(r) : "f"(x)); return r;
}
__device__ __forceinline__ ull fma2(ull a, ull b, ull c) {
    ull d; asm("fma.rn.f32x2 %0, %1, %2, %3;" : "=l"(d) : "l"(a), "l"(b), "l"(c)); return d;
}
__device__ __forceinline__ void unpack2(ull v, float& lo, float& hi) {
    asm("mov.b64 {%0,%1}, %2;" : "=f"(lo), "=f"(hi) : "l"(v));
}
__device__ __forceinline__ uint32_t smem_u32(const void* p) {
    uint32_t a;
    asm("{ .reg .u64 t; cvta.to.shared.u64 t, %1; cvt.u32.u64 %0, t; }" : "=r"(a) : "l"(p));
    return a;
}
__device__ __forceinline__ void bsplit(float f0, float f1, uint32_t& hp, uint32_t& lp) {
    asm("cvt.rn.satfinite.bf16x2.f32 %0, %1, %2;" : "=r"(hp) : "f"(f1), "f"(f0));
    float l0 = f0 - __uint_as_float(hp << 16);
    float l1 = f1 - __uint_as_float(hp & 0xFFFF0000u);
    asm("cvt.rn.satfinite.bf16x2.f32 %0, %1, %2;" : "=r"(lp) : "f"(l1), "f"(l0));
}

#define LDSM4(r0, r1, r2, r3, addr) \
    asm volatile("ldmatrix.sync.aligned.m8n8.x4.shared.b16 {%0,%1,%2,%3}, [%4];" \
        : "=r"(r0), "=r"(r1), "=r"(r2), "=r"(r3) : "r"(addr))

#define MMA16816(d, a0, a1, a2, a3, b0, b1) \
    asm volatile("mma.sync.aligned.m16n8k16.row.col.f32.bf16.bf16.f32 " \
        "{%0,%1,%2,%3},{%4,%5,%6,%7},{%8,%9},{%0,%1,%2,%3};" \
        : "+f"((d)[0]), "+f"((d)[1]), "+f"((d)[2]), "+f"((d)[3]) \
        : "r"(a0), "r"(a1), "r"(a2), "r"(a3), "r"(b0), "r"(b1))

#define CPA16(dst, src) \
    asm volatile("cp.async.cg.shared.global [%0], [%1], 16;" :: "r"(dst), "l"(src))
#define CPA_COMMIT() asm volatile("cp.async.commit_group;")
#define CPA_WAIT0() asm volatile("cp.async.wait_group 0;" ::: "memory")
#define CPA_WAIT1() asm volatile("cp.async.wait_group 1;" ::: "memory")

// ============ K0: coalesced tiled transpose + bf16 hi/lo split ============
// tiles: Wv 512 (64k x 8n), W1 64 (2br x 8k x 4n), W2 16 (2br x 4k x 2n)
__global__ __launch_bounds__(256) void k0_t(const float* __restrict__ W01,
                                            const float* __restrict__ W1f,
                                            const float* __restrict__ W02,
                                            const float* __restrict__ W2f,
                                            const float* __restrict__ Wv) {
    __shared__ float s[32][33];
    int t = blockIdx.x;
    const float* src; unsigned short *dh, *dl;
    int K, N, k0, n0;
    if (t < 512) {
        src = Wv; dh = g_Wvh; dl = g_Wvl; K = 2048; N = 256;
        k0 = (t >> 3) * 32; n0 = (t & 7) * 32;
    } else if (t < 576) {
        int u = t - 512; int br = u >> 5; u &= 31;
        src = br ? W1f : W01; dh = g_W1h + br * 32768; dl = g_W1l + br * 32768;
        K = 256; N = 128;
        k0 = (u >> 2) * 32; n0 = (u & 3) * 32;
    } else {
        int u = t - 576; int br = u >> 3; u &= 7;
        src = br ? W2f : W02; dh = g_W2h + br * 8192; dl = g_W2l + br * 8192;
        K = 128; N = 64;
        k0 = (u >> 1) * 32; n0 = (u & 1) * 32;
    }
    int tx = threadIdx.x & 31, ty = threadIdx.x >> 5;
#pragma unroll
    for (int i = ty; i < 32; i += 8)
        s[i][tx] = src[(k0 + i) * N + n0 + tx];
    __syncthreads();
#pragma unroll
    for (int i = ty; i < 32; i += 8) {
        float x = s[tx][i];
        __nv_bfloat16 hb = __float2bfloat16_rn(x);
        __nv_bfloat16 lb = __float2bfloat16_rn(x - __bfloat162float(hb));
        dh[(n0 + i) * K + k0 + tx] = __bfloat16_as_ushort(hb);
        dl[(n0 + i) * K + k0 + tx] = __bfloat16_as_ushort(lb);
    }
}

// ============ K1: Qp = Q @ Wq + bq ============
__global__ void k1_qp(const float* __restrict__ Q, const float* __restrict__ Wq,
                      const float* __restrict__ bq) {
    __shared__ float qs[QDIM];
    int b = blockIdx.x, tid = threadIdx.x;
    for (int k = tid; k < QDIM; k += 256) qs[k] = Q[b * QDIM + k];
    __syncthreads();
    float a0 = 0.f, a1 = 0.f, a2 = 0.f, a3 = 0.f;
    for (int k = 0; k < QDIM; k += 4) {
        a0 += qs[k + 0] * Wq[(k + 0) * CCH + tid];
        a1 += qs[k + 1] * Wq[(k + 1) * CCH + tid];
        a2 += qs[k + 2] * Wq[(k + 2) * CCH + tid];
        a3 += qs[k + 3] * Wq[(k + 3) * CCH + tid];
    }
    g_Qp[b * CCH + tid] = bq[tid] + ((a0 + a1) + (a2 + a3));
}

// ============ K2: Xp = X @ Wv + bv + Qp[b] on mma.sync bf16 3-split (R12-validated) ============
#define K2_XA 0
#define K2_B0 36864
#define K2_B1 55296
#define K2_SMEM 73728

__device__ __forceinline__ void stage_wv(uint32_t base_u, uint32_t bb, int n0, int c, int tid) {
    for (int t = tid; t < 1024; t += 256) {
        int pl = t >> 9, e = t & 511, n = e >> 3, s = e & 7;
        const unsigned short* src = (pl ? g_Wvl : g_Wvh) + (n0 + n) * 2048 + c * 64 + s * 8;
        CPA16(base_u + bb + (uint32_t)pl * 9216u + (uint32_t)(n * 144 + s * 16), src);
    }
    CPA_COMMIT();
}

__global__ __launch_bounds__(256, 1) void k2_xp(const float* __restrict__ X,
                                                const float* __restrict__ bv) {
    extern __shared__ char raw[];
    uint32_t base_u = smem_u32(raw);
    int tid = threadIdx.x, wid = tid >> 5, lane = tid & 31;
    int n0 = blockIdx.x * 64, m0 = blockIdx.y * 128;

    int m0w = wid * 16;
    uint32_t g = lane >> 3, r = lane & 7;
    uint32_t a_row = (uint32_t)(m0w + (int)(g & 1) * 8 + (int)r);
    uint32_t a_k16 = (g >> 1) * 16;
    uint32_t b_row = (g >> 1) * 8 + r;
    uint32_t b_k16 = (g & 1) * 16;

    int mB = tid >> 1, ksB = (tid & 1) * 32;
    const float* xrow = X + (size_t)(m0 + mB) * IND;

    float acc[32];
#pragma unroll
    for (int q = 0; q < 32; q++) acc[q] = 0.f;
    float4 xr[8];

    stage_wv(base_u, K2_B0, n0, 0, tid);
#pragma unroll
    for (int q = 0; q < 8; q++) xr[q] = *(const float4*)(xrow + ksB + q * 4);

    for (int c = 0; c < 32; c++) {
        uint32_t curB = (c & 1) ? K2_B1 : K2_B0;
        uint32_t nxtB = (c & 1) ? K2_B0 : K2_B1;
        bool hn = (c < 31);
        __syncthreads();
        if (hn) stage_wv(base_u, nxtB, n0, c + 1, tid);
        {
            char* ph = raw + K2_XA + mB * 144 + ksB * 2;
            char* pl = ph + 18432;
#pragma unroll
            for (int q = 0; q < 8; q++) {
                uint32_t hp, lp2;
                bsplit(xr[q].x, xr[q].y, hp, lp2);
                *(uint32_t*)(ph + q * 8) = hp;
                *(uint32_t*)(pl + q * 8) = lp2;
                bsplit(xr[q].z, xr[q].w, hp, lp2);
                *(uint32_t*)(ph + q * 8 + 4) = hp;
                *(uint32_t*)(pl + q * 8 + 4) = lp2;
            }
        }
        if (hn) {
#pragma unroll
            for (int q = 0; q < 8; q++)
                xr[q] = *(const float4*)(xrow + (c + 1) * 64 + ksB + q * 4);
            CPA_WAIT1();
        } else {
            CPA_WAIT0();
        }
        __syncthreads();
#pragma unroll
        for (int kf = 0; kf < 4; kf++) {
            uint32_t ah0, ah1, ah2, ah3, al0, al1, al2, al3;
            uint32_t aA = base_u + K2_XA + a_row * 144 + kf * 32 + a_k16;
            LDSM4(ah0, ah1, ah2, ah3, aA);
            LDSM4(al0, al1, al2, al3, aA + 18432);
#pragma unroll
            for (int nf = 0; nf < 4; nf++) {
                uint32_t bh0, bh1, bh2, bh3, bl0, bl1, bl2, bl3;
                uint32_t aB = base_u + curB + (nf * 16 + b_row) * 144 + kf * 32 + b_k16;
                LDSM4(bh0, bh1, bh2, bh3, aB);
                LDSM4(bl0, bl1, bl2, bl3, aB + 9216);
                float* d0 = &acc[nf * 8];
                MMA16816(d0, ah0, ah1, ah2, ah3, bh0, bh1);
                MMA16816(d0, ah0, ah1, ah2, ah3, bl0, bl1);
                MMA16816(d0, al0, al1, al2, al3, bh0, bh1);
                float* d1 = &acc[nf * 8 + 4];
                MMA16816(d1, ah0, ah1, ah2, ah3, bh2, bh3);
                MMA16816(d1, ah0, ah1, ah2, ah3, bl2, bl3);
                MMA16816(d1, al0, al1, al2, al3, bh2, bh3);
            }
        }
    }
    int ln2 = (lane & 3) * 2;
    int row0 = m0 + m0w + (lane >> 2);
    int row1 = row0 + 8;
    int bi0 = row0 / NRR, bi1 = row1 / NRR;
#pragma unroll
    for (int f = 0; f < 8; f++) {
        int n = n0 + f * 8 + ln2;
        float bv0 = bv[n], bv1 = bv[n + 1];
        g_Xp[row0 * CCH + n]     = acc[f * 4 + 0] + bv0 + g_Qp[bi0 * CCH + n];
        g_Xp[row0 * CCH + n + 1] = acc[f * 4 + 1] + bv1 + g_Qp[bi0 * CCH + n + 1];
        g_Xp[row1 * CCH + n]     = acc[f * 4 + 2] + bv0 + g_Qp[bi1 * CCH + n];
        g_Xp[row1 * CCH + n + 1] = acc[f * 4 + 3] + bv1 + g_Qp[bi1 * CCH + n + 1];
    }
}

// ============ K3: pair-MLP, double-buffered pipeline (R13) — chunk loop NOT unrolled ============
#define OFF_XI  0
#define OFF_XJ  16640
#define OFF_B1S 24960
#define OFF_B2S 25984
#define OFF_W3S 26496
#define OFF_B3S 27008
#define P0_OFF  27136
#define P1_OFF  64000
#define W0_OFF  100864
#define W1B_OFF 137728
#define H1H_B   27136
#define H1L_B   64000
#define W2H_OFF 100864
#define W2L_OFF 118272
#define K3_SMEM 174592

__device__ __forceinline__ void k3_stage_w1(uint32_t base_u, uint32_t wb, int br, int c, int tid) {
    for (int t = tid; t < 2048; t += 256) {
        int pl = t >> 10, e = t & 1023, n = e >> 3, s = e & 7;
        const unsigned short* src = (pl ? g_W1l : g_W1h) + br * 32768 + n * 256 + c * 64 + s * 8;
        CPA16(base_u + wb + (uint32_t)pl * 18432u + (uint32_t)(n * 144 + s * 16), src);
    }
    CPA_COMMIT();
}
__device__ __forceinline__ void k3_stage_w2(uint32_t base_u, int br, int tid) {
    for (int t = tid; t < 2048; t += 256) {
        int pl = t >> 10, e = t & 1023, n = e >> 4, s = e & 15;
        const unsigned short* src = (pl ? g_W2l : g_W2h) + br * 8192 + n * 128 + s * 8;
        CPA16(base_u + (pl ? W2L_OFF : W2H_OFF) + (uint32_t)(n * 272 + s * 16), src);
    }
    CPA_COMMIT();
}
__device__ __forceinline__ void k3_build_p(char* raw, uint32_t pb, int c,
                                           const float* xir, const float* xjr,
                                           int mB, int ksB) {
    char* ph = raw + pb + mB * 144 + ksB * 2;
    char* pl = ph + 18432;
#pragma unroll
    for (int kk = 0; kk < 32; kk += 2) {
        int k = c * 64 + ksB + kk;
        uint32_t hp, lp;
        bsplit(xir[k] * xjr[k], xir[k + 1] * xjr[k + 1], hp, lp);
        *(uint32_t*)(ph + kk * 2) = hp;
        *(uint32_t*)(pl + kk * 2) = lp;
    }
}
__device__ __forceinline__ void k3_mma_g1(float* acc1, uint32_t base_u, uint32_t pb, uint32_t wb,
                                          uint32_t a_row, uint32_t a_k16,
                                          uint32_t b_row, uint32_t b_k16) {
#pragma unroll
    for (int kf = 0; kf < 4; kf++) {
        uint32_t ah0, ah1, ah2, ah3, al0, al1, al2, al3;
        uint32_t aA = base_u + pb + a_row * 144 + kf * 32 + a_k16;
        LDSM4(ah0, ah1, ah2, ah3, aA);
        LDSM4(al0, al1, al2, al3, aA + 18432);
#pragma unroll
        for (int nf = 0; nf < 8; nf++) {
            uint32_t bh0, bh1, bh2, bh3, bl0, bl1, bl2, bl3;
            uint32_t aB = base_u + wb + (nf * 16 + b_row) * 144 + kf * 32 + b_k16;
            LDSM4(bh0, bh1, bh2, bh3, aB);
            LDSM4(bl0, bl1, bl2, bl3, aB + 18432);
            float* d0 = &acc1[nf * 8];
            MMA16816(d0, ah0, ah1, ah2, ah3, bh0, bh1);
            MMA16816(d0, ah0, ah1, ah2, ah3, bl0, bl1);
            MMA16816(d0, al0, al1, al2, al3, bh0, bh1);
            float* d1 = &acc1[nf * 8 + 4];
            MMA16816(d1, ah0, ah1, ah2, ah3, bh2, bh3);
            MMA16816(d1, ah0, ah1, ah2, ah3, bl2, bl3);
            MMA16816(d1, al0, al1, al2, al3, bh2, bh3);
        }
    }
}

__global__ __launch_bounds__(256, 1) void k3_pair(
    const float* __restrict__ b01, const float* __restrict__ b02,
    const float* __restrict__ W03, const float* __restrict__ b03,
    const float* __restrict__ b1f, const float* __restrict__ b2f,
    const float* __restrict__ W3f, const float* __restrict__ b3f) {
    extern __shared__ char raw[];
    uint32_t base_u = smem_u32(raw);

    int tid = threadIdx.x, wid = tid >> 5, lane = tid & 31;
    int b = blockIdx.x / 49;
    int tile = blockIdx.x % 49;
    int it = 0, u = tile, cnt = 13;
    while (u >= cnt) { u -= cnt; it++; cnt -= 2; }
    int jt = 2 * it + u;
    int i0 = it * 16, j0 = jt * 8;

    float* Xi = (float*)(raw + OFF_XI);
    float* Xj = (float*)(raw + OFF_XJ);
    float* b1s = (float*)(raw + OFF_B1S);
    float* b2s = (float*)(raw + OFF_B2S);
    float* w3s = (float*)(raw + OFF_W3S);
    float* b3s = (float*)(raw + OFF_B3S);

    float4 z = make_float4(0.f, 0.f, 0.f, 0.f);
    for (int t = tid; t < 16 * 64; t += 256) {
        int row = t >> 6, c4 = (t & 63) * 4, gi = i0 + row;
        *(float4*)&Xi[row * 260 + c4] =
            (gi < NRR) ? *(const float4*)&g_Xp[(b * NRR + gi) * CCH + c4] : z;
    }
    for (int t = tid; t < 8 * 64; t += 256) {
        int row = t >> 6, c4 = (t & 63) * 4, gj = j0 + row;
        *(float4*)&Xj[row * 260 + c4] =
            (gj < NRR) ? *(const float4*)&g_Xp[(b * NRR + gj) * CCH + c4] : z;
    }
    if (tid < 128) { b1s[tid] = b01[tid]; b1s[128 + tid] = b1f[tid]; }
    if (tid < 64) {
        b2s[tid] = b02[tid]; b2s[64 + tid] = b2f[tid];
        w3s[tid] = W03[tid]; w3s[64 + tid] = W3f[tid];
    }
    if (tid == 0) { b3s[0] = b03[0]; b3s[1] = b3f[0]; }
    __syncthreads();

    int m0w = wid * 16;
    uint32_t g = lane >> 3, r = lane & 7;
    uint32_t a_row = (uint32_t)(m0w + (int)(g & 1) * 8 + (int)r);
    uint32_t a_k16 = (g >> 1) * 16;
    uint32_t b_row = (g >> 1) * 8 + r;
    uint32_t b_k16 = (g & 1) * 16;

    int mB = tid >> 1, ksB = (tid & 1) * 32;
    const float* xir = Xi + (mB >> 3) * 260;
    const float* xjr = Xj + (mB & 7) * 260;
    int ln2 = (lane & 3) * 2;

    for (int br = 0; br < 2; br++) {
        float acc1[64];
#pragma unroll
        for (int q = 0; q < 64; q++) acc1[q] = 0.f;

        k3_stage_w1(base_u, W0_OFF, br, 0, tid);
        k3_build_p(raw, P0_OFF, 0, xir, xjr, mB, ksB);
        CPA_WAIT0();
        __syncthreads();

#pragma unroll 1
        for (int c = 0; c < 4; c++) {
            uint32_t pCur = (c & 1) ? P1_OFF : P0_OFF;
            uint32_t wCur = (c & 1) ? W1B_OFF : W0_OFF;
            uint32_t pNxt = (c & 1) ? P0_OFF : P1_OFF;
            uint32_t wNxt = (c & 1) ? W0_OFF : W1B_OFF;
            if (c < 3) {
                k3_stage_w1(base_u, wNxt, br, c + 1, tid);
                k3_build_p(raw, pNxt, c + 1, xir, xjr, mB, ksB);
            } else {
                k3_stage_w2(base_u, br, tid);
            }
            k3_mma_g1(acc1, base_u, pCur, wCur, a_row, a_k16, b_row, b_k16);
            CPA_WAIT0();
            __syncthreads();
        }

        {
            int rowA = m0w + (lane >> 2);
#pragma unroll
            for (int f = 0; f < 16; f++) {
                int n = f * 8 + ln2;
                int ch = n >> 6, nin = n & 63;
                char* hh = raw + H1H_B + ch * 18432 + nin * 2;
                char* hl = raw + H1L_B + ch * 18432 + nin * 2;
                float c0v = b1s[br * 128 + n], c1v = b1s[br * 128 + n + 1];
                uint32_t hp, lp;
                bsplit(fmaxf(acc1[f * 4 + 0] + c0v, 0.f), fmaxf(acc1[f * 4 + 1] + c1v, 0.f), hp, lp);
                *(uint32_t*)(hh + rowA * 144) = hp;
                *(uint32_t*)(hl + rowA * 144) = lp;
                bsplit(fmaxf(acc1[f * 4 + 2] + c0v, 0.f), fmaxf(acc1[f * 4 + 3] + c1v, 0.f), hp, lp);
                *(uint32_t*)(hh + (rowA + 8) * 144) = hp;
                *(uint32_t*)(hl + (rowA + 8) * 144) = lp;
            }
        }
        __syncthreads();

        float acc2[32];
#pragma unroll
        for (int q = 0; q < 32; q++) acc2[q] = 0.f;
#pragma unroll
        for (int kf = 0; kf < 8; kf++) {
            int ch = kf >> 2, kfin = kf & 3;
            uint32_t ah0, ah1, ah2, ah3, al0, al1, al2, al3;
            uint32_t aAh = base_u + H1H_B + ch * 18432 + a_row * 144 + kfin * 32 + a_k16;
            uint32_t aAl = base_u + H1L_B + ch * 18432 + a_row * 144 + kfin * 32 + a_k16;
            LDSM4(ah0, ah1, ah2, ah3, aAh);
            LDSM4(al0, al1, al2, al3, aAl);
#pragma unroll
            for (int nf = 0; nf < 4; nf++) {
                uint32_t bh0, bh1, bh2, bh3, bl0, bl1, bl2, bl3;
                uint32_t aB = base_u + W2H_OFF + (nf * 16 + b_row) * 272 + kf * 32 + b_k16;
                LDSM4(bh0, bh1, bh2, bh3, aB);
                LDSM4(bl0, bl1, bl2, bl3, aB + 17408);
                float* d0 = &acc2[nf * 8];
                MMA16816(d0, ah0, ah1, ah2, ah3, bh0, bh1);
                MMA16816(d0, ah0, ah1, ah2, ah3, bl0, bl1);
                MMA16816(d0, al0, al1, al2, al3, bh0, bh1);
                float* d1 = &acc2[nf * 8 + 4];
                MMA16816(d1, ah0, ah1, ah2, ah3, bh2, bh3);
                MMA16816(d1, ah0, ah1, ah2, ah3, bl2, bl3);
                MMA16816(d1, al0, al1, al2, al3, bh2, bh3);
            }
        }

        {
            float p0 = 0.f, p1 = 0.f;
#pragma unroll
            for (int f = 0; f < 8; f++) {
                int n = f * 8 + ln2;
                float w0 = w3s[br * 64 + n], w1 = w3s[br * 64 + n + 1];
                float c0 = b2s[br * 64 + n], c1 = b2s[br * 64 + n + 1];
                p0 += fmaxf(acc2[f * 4 + 0] + c0, 0.f) * w0
                    + fmaxf(acc2[f * 4 + 1] + c1, 0.f) * w1;
                p1 += fmaxf(acc2[f * 4 + 2] + c0, 0.f) * w0
                    + fmaxf(acc2[f * 4 + 3] + c1, 0.f) * w1;
            }
            p0 += __shfl_xor_sync(~0u, p0, 1); p0 += __shfl_xor_sync(~0u, p0, 2);
            p1 += __shfl_xor_sync(~0u, p1, 1); p1 += __shfl_xor_sync(~0u, p1, 2);
            if ((lane & 3) == 0) {
                int q = lane >> 2;
                float* L = g_logits + (br * BS + b) * (NRR * NRR);
                int m1 = m0w + q, m2 = m0w + q + 8;
                float v0 = 2.f * fmaxf(p0 + b3s[br], 0.f);
                float v1 = 2.f * fmaxf(p1 + b3s[br], 0.f);
                int i1 = i0 + (m1 >> 3), j1 = j0 + (m1 & 7);
                int i2 = i0 + (m2 >> 3), j2 = j0 + (m2 & 7);
                if (i1 < NRR && j1 < NRR) { L[i1 * NRR + j1] = v0; L[j1 * NRR + i1] = v0; }
                if (i2 < NRR && j2 < NRR) { L[i2 * NRR + j2] = v1; L[j2 * NRR + i2] = v1; }
            }
        }
        __syncthreads();
    }
}

// ============ K4: per-(br,b) softmax stats only ============
__global__ __launch_bounds__(512) void k4_stats() {
    int id = blockIdx.x, tid = threadIdx.x;
    __shared__ float red[16];
    __shared__ float mm_s;
    const int NE = NRR * NRR;
    const float* L = g_logits + id * NE;
    float m = -1e30f;
    for (int e = tid; e < NE; e += 512) m = fmaxf(m, L[e]);
    for (int o = 16; o; o >>= 1) m = fmaxf(m, __shfl_xor_sync(~0u, m, o));
    if ((tid & 31) == 0) red[tid >> 5] = m;
    __syncthreads();
    if (tid == 0) {
        float a = red[0];
        for (int w = 1; w < 16; w++) a = fmaxf(a, red[w]);
        mm_s = a;
        g_bm[id] = a;
    }
    __syncthreads();
    float mm = mm_s, s = 0.f;
    for (int e = tid; e < NE; e += 512) s += __expf(L[e] - mm);
    for (int o = 16; o; o >>= 1) s += __shfl_xor_sync(~0u, s, o);
    if ((tid & 31) == 0) red[tid >> 5] = s;
    __syncthreads();
    if (tid == 0) {
        float a = red[0];
        for (int w = 1; w < 16; w++) a += red[w];
        g_bsum[id] = a;
    }
}

// ============ K5: out = S @ X with S built inline from logits ============
__global__ __launch_bounds__(256) void k5_out(const float* __restrict__ X,
                                              float* __restrict__ out) {
    __shared__ float Ss[NRR * NRR];
    int b = blockIdx.y, tid = threadIdx.x;
    const int NE = NRR * NRR;
    float m0 = g_bm[b], is0 = 1.f / g_bsum[b];
    float m1 = g_bm[BS + b], is1 = 1.f / g_bsum[BS + b];
    const float* L0 = g_logits + b * NE;
    const float* L1 = g_logits + (BS + b) * NE;
    for (int e = tid; e < NE; e += 256)
        Ss[e] = 0.5f * (__expf(L0[e] - m0) * is0 + __expf(L1[e] - m1) * is1);
    __syncthreads();
    int tx = tid & 63, ty = tid >> 6;
    int c0 = blockIdx.x * 256 + tx * 4;
    int i0 = ty * 25;
    const float* Xb = X + b * NRR * IND;
    ull a01[25], a23[25];
#pragma unroll
    for (int ii = 0; ii < 25; ii++) { a01[ii] = 0ULL; a23[ii] = 0ULL; }
    for (int j = 0; j < NRR; j++) {
        float4 xv = *(const float4*)&Xb[j * IND + c0];
        ull x01, x23;
        asm("mov.b64 %0, {%1,%2};" : "=l"(x01) : "f"(xv.x), "f"(xv.y));
        asm("mov.b64 %0, {%1,%2};" : "=l"(x23) : "f"(xv.z), "f"(xv.w));
#pragma unroll
        for (int ii = 0; ii < 25; ii++) {
            ull s2 = pack2(Ss[(i0 + ii) * NRR + j]);
            a01[ii] = fma2(s2, x01, a01[ii]);
            a23[ii] = fma2(s2, x23, a23[ii]);
        }
    }
#pragma unroll
    for (int ii = 0; ii < 25; ii++) {
        float4 o;
        unpack2(a01[ii], o.x, o.y);
        unpack2(a23[ii], o.z, o.w);
        *(float4*)&out[(b * NRR + i0 + ii) * IND + c0] = o;
    }
}

// ============ launch ============
extern "C" void kernel_launch(void* const* d_in, const int* in_sizes, int n_in,
                              void* d_out, int out_size) {
    const float* Q   = (const float*)d_in[0];
    const float* X   = (const float*)d_in[1];
    const float* Wv  = (const float*)d_in[2];
    const float* bv  = (const float*)d_in[3];
    const float* Wq  = (const float*)d_in[4];
    const float* bq  = (const float*)d_in[5];
    const float* W01 = (const float*)d_in[6];
    const float* b01 = (const float*)d_in[7];
    const float* W02 = (const float*)d_in[8];
    const float* b02 = (const float*)d_in[9];
    const float* W03 = (const float*)d_in[10];
    const float* b03 = (const float*)d_in[11];
    const float* W1  = (const float*)d_in[12];
    const float* b1  = (const float*)d_in[13];
    const float* W2  = (const float*)d_in[14];
    const float* b2  = (const float*)d_in[15];
    const float* W3  = (const float*)d_in[16];
    const float* b3  = (const float*)d_in[17];
    float* out = (float*)d_out;

    cudaFuncSetAttribute(k2_xp, cudaFuncAttributeMaxDynamicSharedMemorySize, K2_SMEM);
    cudaFuncSetAttribute(k3_pair, cudaFuncAttributeMaxDynamicSharedMemorySize, K3_SMEM);

    k0_t<<<592, 256>>>(W01, W1, W02, W2, Wv);
    k1_qp<<<BS, 256>>>(Q, Wq, bq);
    k2_xp<<<dim3(4, 25), 256, K2_SMEM>>>(X, bv);
    k3_pair<<<BS * 49, 256, K3_SMEM>>>(b01, b02, W03, b03, b1, b2, W3, b3);
    k4_stats<<<2 * BS, 512>>>();
    k5_out<<<dim3(8, BS), 256>>>(X, out);
}

// round 15
// speedup vs baseline: 1.0562x; 1.0562x over previous
#include <cuda_runtime.h>
#include <cuda_bf16.h>
#include <math.h>
#include <stdint.h>

typedef unsigned long long ull;

#define BS 32
#define NRR 100
#define IND 2048
#define QDIM 1024
#define CCH 256

__device__ float g_Qp[BS * CCH];
__device__ float g_Xp[BS * NRR * CCH];
__device__ float g_logits[2 * BS * NRR * NRR];
__device__ float g_S[BS * NRR * NRR];
__device__ __align__(16) unsigned short g_W1h[2 * 128 * 256];
__device__ __align__(16) unsigned short g_W1l[2 * 128 * 256];
__device__ __align__(16) unsigned short g_W2h[2 * 64 * 128];
__device__ __align__(16) unsigned short g_W2l[2 * 64 * 128];
__device__ __align__(16) unsigned short g_Wvh[256 * 2048];
__device__ __align__(16) unsigned short g_Wvl[256 * 2048];

__device__ __forceinline__ ull pack2(float x) {
    ull r; asm("mov.b64 %0, {%1,%1};" : "=l"(r) : "f"(x)); return r;
}
__device__ __forceinline__ ull fma2(ull a, ull b, ull c) {
    ull d; asm("fma.rn.f32x2 %0, %1, %2, %3;" : "=l"(d) : "l"(a), "l"(b), "l"(c)); return d;
}
__device__ __forceinline__ void unpack2(ull v, float& lo, float& hi) {
    asm("mov.b64 {%0,%1}, %2;" : "=f"(lo), "=f"(hi) : "l"(v));
}
__device__ __forceinline__ uint32_t smem_u32(const void* p) {
    uint32_t a;
    asm("{ .reg .u64 t; cvta.to.shared.u64 t, %1; cvt.u32.u64 %0, t; }" : "=r"(a) : "l"(p));
    return a;
}
__device__ __forceinline__ void bsplit(float f0, float f1, uint32_t& hp, uint32_t& lp) {
    asm("cvt.rn.satfinite.bf16x2.f32 %0, %1, %2;" : "=r"(hp) : "f"(f1), "f"(f0));
    float l0 = f0 - __uint_as_float(hp << 16);
    float l1 = f1 - __uint_as_float(hp & 0xFFFF0000u);
    asm("cvt.rn.satfinite.bf16x2.f32 %0, %1, %2;" : "=r"(lp) : "f"(l1), "f"(l0));
}

#define LDSM4(r0, r1, r2, r3, addr) \
    asm volatile("ldmatrix.sync.aligned.m8n8.x4.shared.b16 {%0,%1,%2,%3}, [%4];" \
        : "=r"(r0), "=r"(r1), "=r"(r2), "=r"(r3) : "r"(addr))

#define MMA16816(d, a0, a1, a2, a3, b0, b1) \
    asm volatile("mma.sync.aligned.m16n8k16.row.col.f32.bf16.bf16.f32 " \
        "{%0,%1,%2,%3},{%4,%5,%6,%7},{%8,%9},{%0,%1,%2,%3};" \
        : "+f"((d)[0]), "+f"((d)[1]), "+f"((d)[2]), "+f"((d)[3]) \
        : "r"(a0), "r"(a1), "r"(a2), "r"(a3), "r"(b0), "r"(b1))

#define CPA16(dst, src) \
    asm volatile("cp.async.cg.shared.global [%0], [%1], 16;" :: "r"(dst), "l"(src))
#define CPA_COMMIT() asm volatile("cp.async.commit_group;")
#define CPA_WAIT0() asm volatile("cp.async.wait_group 0;" ::: "memory")
#define CPA_WAIT1() asm volatile("cp.async.wait_group 1;" ::: "memory")

// ============ K0: coalesced tiled transpose + bf16 hi/lo split (R14-validated) ============
__global__ __launch_bounds__(256) void k0_t(const float* __restrict__ W01,
                                            const float* __restrict__ W1f,
                                            const float* __restrict__ W02,
                                            const float* __restrict__ W2f,
                                            const float* __restrict__ Wv) {
    __shared__ float s[32][33];
    int t = blockIdx.x;
    const float* src; unsigned short *dh, *dl;
    int K, N, k0, n0;
    if (t < 512) {
        src = Wv; dh = g_Wvh; dl = g_Wvl; K = 2048; N = 256;
        k0 = (t >> 3) * 32; n0 = (t & 7) * 32;
    } else if (t < 576) {
        int u = t - 512; int br = u >> 5; u &= 31;
        src = br ? W1f : W01; dh = g_W1h + br * 32768; dl = g_W1l + br * 32768;
        K = 256; N = 128;
        k0 = (u >> 2) * 32; n0 = (u & 3) * 32;
    } else {
        int u = t - 576; int br = u >> 3; u &= 7;
        src = br ? W2f : W02; dh = g_W2h + br * 8192; dl = g_W2l + br * 8192;
        K = 128; N = 64;
        k0 = (u >> 1) * 32; n0 = (u & 1) * 32;
    }
    int tx = threadIdx.x & 31, ty = threadIdx.x >> 5;
#pragma unroll
    for (int i = ty; i < 32; i += 8)
        s[i][tx] = src[(k0 + i) * N + n0 + tx];
    __syncthreads();
#pragma unroll
    for (int i = ty; i < 32; i += 8) {
        float x = s[tx][i];
        __nv_bfloat16 hb = __float2bfloat16_rn(x);
        __nv_bfloat16 lb = __float2bfloat16_rn(x - __bfloat162float(hb));
        dh[(n0 + i) * K + k0 + tx] = __bfloat16_as_ushort(hb);
        dl[(n0 + i) * K + k0 + tx] = __bfloat16_as_ushort(lb);
    }
}

// ============ K1: Qp = Q @ Wq + bq ============
__global__ void k1_qp(const float* __restrict__ Q, const float* __restrict__ Wq,
                      const float* __restrict__ bq) {
    __shared__ float qs[QDIM];
    int b = blockIdx.x, tid = threadIdx.x;
    for (int k = tid; k < QDIM; k += 256) qs[k] = Q[b * QDIM + k];
    __syncthreads();
    float a0 = 0.f, a1 = 0.f, a2 = 0.f, a3 = 0.f;
    for (int k = 0; k < QDIM; k += 4) {
        a0 += qs[k + 0] * Wq[(k + 0) * CCH + tid];
        a1 += qs[k + 1] * Wq[(k + 1) * CCH + tid];
        a2 += qs[k + 2] * Wq[(k + 2) * CCH + tid];
        a3 += qs[k + 3] * Wq[(k + 3) * CCH + tid];
    }
    g_Qp[b * CCH + tid] = bq[tid] + ((a0 + a1) + (a2 + a3));
}

// ============ K2: Xp = X @ Wv + bv + Qp[b] on mma.sync bf16 3-split (R12-validated) ============
#define K2_XA 0
#define K2_B0 36864
#define K2_B1 55296
#define K2_SMEM 73728

__device__ __forceinline__ void stage_wv(uint32_t base_u, uint32_t bb, int n0, int c, int tid) {
    for (int t = tid; t < 1024; t += 256) {
        int pl = t >> 9, e = t & 511, n = e >> 3, s = e & 7;
        const unsigned short* src = (pl ? g_Wvl : g_Wvh) + (n0 + n) * 2048 + c * 64 + s * 8;
        CPA16(base_u + bb + (uint32_t)pl * 9216u + (uint32_t)(n * 144 + s * 16), src);
    }
    CPA_COMMIT();
}

__global__ __launch_bounds__(256, 1) void k2_xp(const float* __restrict__ X,
                                                const float* __restrict__ bv) {
    extern __shared__ char raw[];
    uint32_t base_u = smem_u32(raw);
    int tid = threadIdx.x, wid = tid >> 5, lane = tid & 31;
    int n0 = blockIdx.x * 64, m0 = blockIdx.y * 128;

    int m0w = wid * 16;
    uint32_t g = lane >> 3, r = lane & 7;
    uint32_t a_row = (uint32_t)(m0w + (int)(g & 1) * 8 + (int)r);
    uint32_t a_k16 = (g >> 1) * 16;
    uint32_t b_row = (g >> 1) * 8 + r;
    uint32_t b_k16 = (g & 1) * 16;

    int mB = tid >> 1, ksB = (tid & 1) * 32;
    const float* xrow = X + (size_t)(m0 + mB) * IND;

    float acc[32];
#pragma unroll
    for (int q = 0; q < 32; q++) acc[q] = 0.f;
    float4 xr[8];

    stage_wv(base_u, K2_B0, n0, 0, tid);
#pragma unroll
    for (int q = 0; q < 8; q++) xr[q] = *(const float4*)(xrow + ksB + q * 4);

    for (int c = 0; c < 32; c++) {
        uint32_t curB = (c & 1) ? K2_B1 : K2_B0;
        uint32_t nxtB = (c & 1) ? K2_B0 : K2_B1;
        bool hn = (c < 31);
        __syncthreads();
        if (hn) stage_wv(base_u, nxtB, n0, c + 1, tid);
        {
            char* ph = raw + K2_XA + mB * 144 + ksB * 2;
            char* pl = ph + 18432;
#pragma unroll
            for (int q = 0; q < 8; q++) {
                uint32_t hp, lp2;
                bsplit(xr[q].x, xr[q].y, hp, lp2);
                *(uint32_t*)(ph + q * 8) = hp;
                *(uint32_t*)(pl + q * 8) = lp2;
                bsplit(xr[q].z, xr[q].w, hp, lp2);
                *(uint32_t*)(ph + q * 8 + 4) = hp;
                *(uint32_t*)(pl + q * 8 + 4) = lp2;
            }
        }
        if (hn) {
#pragma unroll
            for (int q = 0; q < 8; q++)
                xr[q] = *(const float4*)(xrow + (c + 1) * 64 + ksB + q * 4);
            CPA_WAIT1();
        } else {
            CPA_WAIT0();
        }
        __syncthreads();
#pragma unroll
        for (int kf = 0; kf < 4; kf++) {
            uint32_t ah0, ah1, ah2, ah3, al0, al1, al2, al3;
            uint32_t aA = base_u + K2_XA + a_row * 144 + kf * 32 + a_k16;
            LDSM4(ah0, ah1, ah2, ah3, aA);
            LDSM4(al0, al1, al2, al3, aA + 18432);
#pragma unroll
            for (int nf = 0; nf < 4; nf++) {
                uint32_t bh0, bh1, bh2, bh3, bl0, bl1, bl2, bl3;
                uint32_t aB = base_u + curB + (nf * 16 + b_row) * 144 + kf * 32 + b_k16;
                LDSM4(bh0, bh1, bh2, bh3, aB);
                LDSM4(bl0, bl1, bl2, bl3, aB + 9216);
                float* d0 = &acc[nf * 8];
                MMA16816(d0, ah0, ah1, ah2, ah3, bh0, bh1);
                MMA16816(d0, ah0, ah1, ah2, ah3, bl0, bl1);
                MMA16816(d0, al0, al1, al2, al3, bh0, bh1);
                float* d1 = &acc[nf * 8 + 4];
                MMA16816(d1, ah0, ah1, ah2, ah3, bh2, bh3);
                MMA16816(d1, ah0, ah1, ah2, ah3, bl2, bl3);
                MMA16816(d1, al0, al1, al2, al3, bh2, bh3);
            }
        }
    }
    int ln2 = (lane & 3) * 2;
    int row0 = m0 + m0w + (lane >> 2);
    int row1 = row0 + 8;
    int bi0 = row0 / NRR, bi1 = row1 / NRR;
#pragma unroll
    for (int f = 0; f < 8; f++) {
        int n = n0 + f * 8 + ln2;
        float bv0 = bv[n], bv1 = bv[n + 1];
        g_Xp[row0 * CCH + n]     = acc[f * 4 + 0] + bv0 + g_Qp[bi0 * CCH + n];
        g_Xp[row0 * CCH + n + 1] = acc[f * 4 + 1] + bv1 + g_Qp[bi0 * CCH + n + 1];
        g_Xp[row1 * CCH + n]     = acc[f * 4 + 2] + bv0 + g_Qp[bi1 * CCH + n];
        g_Xp[row1 * CCH + n + 1] = acc[f * 4 + 3] + bv1 + g_Qp[bi1 * CCH + n + 1];
    }
}

// ============ K3: pair-MLP, double-buffered pipeline — R13 VERBATIM (full unroll) ============
#define OFF_XI  0
#define OFF_XJ  16640
#define OFF_B1S 24960
#define OFF_B2S 25984
#define OFF_W3S 26496
#define OFF_B3S 27008
#define P0_OFF  27136
#define P1_OFF  64000
#define W0_OFF  100864
#define W1B_OFF 137728
#define H1H_B   27136
#define H1L_B   64000
#define W2H_OFF 100864
#define W2L_OFF 118272
#define K3_SMEM 174592

__device__ __forceinline__ void k3_stage_w1(uint32_t base_u, uint32_t wb, int br, int c, int tid) {
    for (int t = tid; t < 2048; t += 256) {
        int pl = t >> 10, e = t & 1023, n = e >> 3, s = e & 7;
        const unsigned short* src = (pl ? g_W1l : g_W1h) + br * 32768 + n * 256 + c * 64 + s * 8;
        CPA16(base_u + wb + (uint32_t)pl * 18432u + (uint32_t)(n * 144 + s * 16), src);
    }
    CPA_COMMIT();
}
__device__ __forceinline__ void k3_stage_w2(uint32_t base_u, int br, int tid) {
    for (int t = tid; t < 2048; t += 256) {
        int pl = t >> 10, e = t & 1023, n = e >> 4, s = e & 15;
        const unsigned short* src = (pl ? g_W2l : g_W2h) + br * 8192 + n * 128 + s * 8;
        CPA16(base_u + (pl ? W2L_OFF : W2H_OFF) + (uint32_t)(n * 272 + s * 16), src);
    }
    CPA_COMMIT();
}
__device__ __forceinline__ void k3_build_p(char* raw, uint32_t pb, int c,
                                           const float* xir, const float* xjr,
                                           int mB, int ksB) {
    char* ph = raw + pb + mB * 144 + ksB * 2;
    char* pl = ph + 18432;
#pragma unroll
    for (int kk = 0; kk < 32; kk += 2) {
        int k = c * 64 + ksB + kk;
        uint32_t hp, lp;
        bsplit(xir[k] * xjr[k], xir[k + 1] * xjr[k + 1], hp, lp);
        *(uint32_t*)(ph + kk * 2) = hp;
        *(uint32_t*)(pl + kk * 2) = lp;
    }
}
__device__ __forceinline__ void k3_mma_g1(float* acc1, uint32_t base_u, uint32_t pb, uint32_t wb,
                                          uint32_t a_row, uint32_t a_k16,
                                          uint32_t b_row, uint32_t b_k16) {
#pragma unroll
    for (int kf = 0; kf < 4; kf++) {
        uint32_t ah0, ah1, ah2, ah3, al0, al1, al2, al3;
        uint32_t aA = base_u + pb + a_row * 144 + kf * 32 + a_k16;
        LDSM4(ah0, ah1, ah2, ah3, aA);
        LDSM4(al0, al1, al2, al3, aA + 18432);
#pragma unroll
        for (int nf = 0; nf < 8; nf++) {
            uint32_t bh0, bh1, bh2, bh3, bl0, bl1, bl2, bl3;
            uint32_t aB = base_u + wb + (nf * 16 + b_row) * 144 + kf * 32 + b_k16;
            LDSM4(bh0, bh1, bh2, bh3, aB);
            LDSM4(bl0, bl1, bl2, bl3, aB + 18432);
            float* d0 = &acc1[nf * 8];
            MMA16816(d0, ah0, ah1, ah2, ah3, bh0, bh1);
            MMA16816(d0, ah0, ah1, ah2, ah3, bl0, bl1);
            MMA16816(d0, al0, al1, al2, al3, bh0, bh1);
            float* d1 = &acc1[nf * 8 + 4];
            MMA16816(d1, ah0, ah1, ah2, ah3, bh2, bh3);
            MMA16816(d1, ah0, ah1, ah2, ah3, bl2, bl3);
            MMA16816(d1, al0, al1, al2, al3, bh2, bh3);
        }
    }
}

__global__ __launch_bounds__(256, 1) void k3_pair(
    const float* __restrict__ b01, const float* __restrict__ b02,
    const float* __restrict__ W03, const float* __restrict__ b03,
    const float* __restrict__ b1f, const float* __restrict__ b2f,
    const float* __restrict__ W3f, const float* __restrict__ b3f) {
    extern __shared__ char raw[];
    uint32_t base_u = smem_u32(raw);

    int tid = threadIdx.x, wid = tid >> 5, lane = tid & 31;
    int b = blockIdx.x / 49;
    int tile = blockIdx.x % 49;
    int it = 0, u = tile, cnt = 13;
    while (u >= cnt) { u -= cnt; it++; cnt -= 2; }
    int jt = 2 * it + u;
    int i0 = it * 16, j0 = jt * 8;

    float* Xi = (float*)(raw + OFF_XI);
    float* Xj = (float*)(raw + OFF_XJ);
    float* b1s = (float*)(raw + OFF_B1S);
    float* b2s = (float*)(raw + OFF_B2S);
    float* w3s = (float*)(raw + OFF_W3S);
    float* b3s = (float*)(raw + OFF_B3S);

    float4 z = make_float4(0.f, 0.f, 0.f, 0.f);
    for (int t = tid; t < 16 * 64; t += 256) {
        int row = t >> 6, c4 = (t & 63) * 4, gi = i0 + row;
        *(float4*)&Xi[row * 260 + c4] =
            (gi < NRR) ? *(const float4*)&g_Xp[(b * NRR + gi) * CCH + c4] : z;
    }
    for (int t = tid; t < 8 * 64; t += 256) {
        int row = t >> 6, c4 = (t & 63) * 4, gj = j0 + row;
        *(float4*)&Xj[row * 260 + c4] =
            (gj < NRR) ? *(const float4*)&g_Xp[(b * NRR + gj) * CCH + c4] : z;
    }
    if (tid < 128) { b1s[tid] = b01[tid]; b1s[128 + tid] = b1f[tid]; }
    if (tid < 64) {
        b2s[tid] = b02[tid]; b2s[64 + tid] = b2f[tid];
        w3s[tid] = W03[tid]; w3s[64 + tid] = W3f[tid];
    }
    if (tid == 0) { b3s[0] = b03[0]; b3s[1] = b3f[0]; }
    __syncthreads();

    int m0w = wid * 16;
    uint32_t g = lane >> 3, r = lane & 7;
    uint32_t a_row = (uint32_t)(m0w + (int)(g & 1) * 8 + (int)r);
    uint32_t a_k16 = (g >> 1) * 16;
    uint32_t b_row = (g >> 1) * 8 + r;
    uint32_t b_k16 = (g & 1) * 16;

    int mB = tid >> 1, ksB = (tid & 1) * 32;
    const float* xir = Xi + (mB >> 3) * 260;
    const float* xjr = Xj + (mB & 7) * 260;
    int ln2 = (lane & 3) * 2;

    for (int br = 0; br < 2; br++) {
        float acc1[64];
#pragma unroll
        for (int q = 0; q < 64; q++) acc1[q] = 0.f;

        k3_stage_w1(base_u, W0_OFF, br, 0, tid);
        k3_build_p(raw, P0_OFF, 0, xir, xjr, mB, ksB);
        CPA_WAIT0();
        __syncthreads();

#pragma unroll
        for (int c = 0; c < 4; c++) {
            uint32_t pCur = (c & 1) ? P1_OFF : P0_OFF;
            uint32_t wCur = (c & 1) ? W1B_OFF : W0_OFF;
            uint32_t pNxt = (c & 1) ? P0_OFF : P1_OFF;
            uint32_t wNxt = (c & 1) ? W0_OFF : W1B_OFF;
            if (c < 3) {
                k3_stage_w1(base_u, wNxt, br, c + 1, tid);
                k3_build_p(raw, pNxt, c + 1, xir, xjr, mB, ksB);
            } else {
                k3_stage_w2(base_u, br, tid);
            }
            k3_mma_g1(acc1, base_u, pCur, wCur, a_row, a_k16, b_row, b_k16);
            CPA_WAIT0();
            __syncthreads();
        }

        {
            int rowA = m0w + (lane >> 2);
#pragma unroll
            for (int f = 0; f < 16; f++) {
                int n = f * 8 + ln2;
                int ch = n >> 6, nin = n & 63;
                char* hh = raw + H1H_B + ch * 18432 + nin * 2;
                char* hl = raw + H1L_B + ch * 18432 + nin * 2;
                float c0v = b1s[br * 128 + n], c1v = b1s[br * 128 + n + 1];
                uint32_t hp, lp;
                bsplit(fmaxf(acc1[f * 4 + 0] + c0v, 0.f), fmaxf(acc1[f * 4 + 1] + c1v, 0.f), hp, lp);
                *(uint32_t*)(hh + rowA * 144) = hp;
                *(uint32_t*)(hl + rowA * 144) = lp;
                bsplit(fmaxf(acc1[f * 4 + 2] + c0v, 0.f), fmaxf(acc1[f * 4 + 3] + c1v, 0.f), hp, lp);
                *(uint32_t*)(hh + (rowA + 8) * 144) = hp;
                *(uint32_t*)(hl + (rowA + 8) * 144) = lp;
            }
        }
        __syncthreads();

        float acc2[32];
#pragma unroll
        for (int q = 0; q < 32; q++) acc2[q] = 0.f;
#pragma unroll
        for (int kf = 0; kf < 8; kf++) {
            int ch = kf >> 2, kfin = kf & 3;
            uint32_t ah0, ah1, ah2, ah3, al0, al1, al2, al3;
            uint32_t aAh = base_u + H1H_B + ch * 18432 + a_row * 144 + kfin * 32 + a_k16;
            uint32_t aAl = base_u + H1L_B + ch * 18432 + a_row * 144 + kfin * 32 + a_k16;
            LDSM4(ah0, ah1, ah2, ah3, aAh);
            LDSM4(al0, al1, al2, al3, aAl);
#pragma unroll
            for (int nf = 0; nf < 4; nf++) {
                uint32_t bh0, bh1, bh2, bh3, bl0, bl1, bl2, bl3;
                uint32_t aB = base_u + W2H_OFF + (nf * 16 + b_row) * 272 + kf * 32 + b_k16;
                LDSM4(bh0, bh1, bh2, bh3, aB);
                LDSM4(bl0, bl1, bl2, bl3, aB + 17408);
                float* d0 = &acc2[nf * 8];
                MMA16816(d0, ah0, ah1, ah2, ah3, bh0, bh1);
                MMA16816(d0, ah0, ah1, ah2, ah3, bl0, bl1);
                MMA16816(d0, al0, al1, al2, al3, bh0, bh1);
                float* d1 = &acc2[nf * 8 + 4];
                MMA16816(d1, ah0, ah1, ah2, ah3, bh2, bh3);
                MMA16816(d1, ah0, ah1, ah2, ah3, bl2, bl3);
                MMA16816(d1, al0, al1, al2, al3, bh2, bh3);
            }
        }

        {
            float p0 = 0.f, p1 = 0.f;
#pragma unroll
            for (int f = 0; f < 8; f++) {
                int n = f * 8 + ln2;
                float w0 = w3s[br * 64 + n], w1 = w3s[br * 64 + n + 1];
                float c0 = b2s[br * 64 + n], c1 = b2s[br * 64 + n + 1];
                p0 += fmaxf(acc2[f * 4 + 0] + c0, 0.f) * w0
                    + fmaxf(acc2[f * 4 + 1] + c1, 0.f) * w1;
                p1 += fmaxf(acc2[f * 4 + 2] + c0, 0.f) * w0
                    + fmaxf(acc2[f * 4 + 3] + c1, 0.f) * w1;
            }
            p0 += __shfl_xor_sync(~0u, p0, 1); p0 += __shfl_xor_sync(~0u, p0, 2);
            p1 += __shfl_xor_sync(~0u, p1, 1); p1 += __shfl_xor_sync(~0u, p1, 2);
            if ((lane & 3) == 0) {
                int q = lane >> 2;
                float* L = g_logits + (br * BS + b) * (NRR * NRR);
                int m1 = m0w + q, m2 = m0w + q + 8;
                float v0 = 2.f * fmaxf(p0 + b3s[br], 0.f);
                float v1 = 2.f * fmaxf(p1 + b3s[br], 0.f);
                int i1 = i0 + (m1 >> 3), j1 = j0 + (m1 & 7);
                int i2 = i0 + (m2 >> 3), j2 = j0 + (m2 & 7);
                if (i1 < NRR && j1 < NRR) { L[i1 * NRR + j1] = v0; L[j1 * NRR + i1] = v0; }
                if (i2 < NRR && j2 < NRR) { L[i2 * NRR + j2] = v1; L[j2 * NRR + i2] = v1; }
            }
        }
        __syncthreads();
    }
}

// ============ K4: softmax per (b,branch) + combine (R13 verbatim) ============
__global__ __launch_bounds__(512) void k4_softmax() {
    int b = blockIdx.x, tid = threadIdx.x;
    __shared__ float red[16];
    __shared__ float bm[2], bsum[2];
    const int NE = NRR * NRR;
    for (int br = 0; br < 2; br++) {
        const float* L = g_logits + (br * BS + b) * NE;
        float m = -1e30f;
        for (int e = tid; e < NE; e += 512) m = fmaxf(m, L[e]);
        for (int o = 16; o; o >>= 1) m = fmaxf(m, __shfl_xor_sync(~0u, m, o));
        if ((tid & 31) == 0) red[tid >> 5] = m;
        __syncthreads();
        if (tid == 0) {
            float a = red[0];
            for (int w = 1; w < 16; w++) a = fmaxf(a, red[w]);
            bm[br] = a;
        }
        __syncthreads();
        float mm = bm[br], s = 0.f;
        for (int e = tid; e < NE; e += 512) s += __expf(L[e] - mm);
        for (int o = 16; o; o >>= 1) s += __shfl_xor_sync(~0u, s, o);
        if ((tid & 31) == 0) red[tid >> 5] = s;
        __syncthreads();
        if (tid == 0) {
            float a = red[0];
            for (int w = 1; w < 16; w++) a += red[w];
            bsum[br] = a;
        }
        __syncthreads();
    }
    float m0 = bm[0], is0 = 1.f / bsum[0];
    float m1 = bm[1], is1 = 1.f / bsum[1];
    const float* L0 = g_logits + b * NE;
    const float* L1 = g_logits + (BS + b) * NE;
    float* S = g_S + b * NE;
    for (int e = tid; e < NE; e += 512)
        S[e] = 0.5f * (__expf(L0[e] - m0) * is0 + __expf(L1[e] - m1) * is1);
}

// ============ K5: out = S @ X (f32x2, row split) (R13 verbatim) ============
__global__ __launch_bounds__(256) void k5_out(const float* __restrict__ X,
                                              float* __restrict__ out) {
    __shared__ float Ss[NRR * NRR];
    int b = blockIdx.y, tid = threadIdx.x;
    for (int e = tid; e < NRR * NRR; e += 256) Ss[e] = g_S[b * NRR * NRR + e];
    __syncthreads();
    int tx = tid & 63, ty = tid >> 6;
    int c0 = blockIdx.x * 256 + tx * 4;
    int i0 = ty * 25;
    const float* Xb = X + b * NRR * IND;
    ull a01[25], a23[25];
#pragma unroll
    for (int ii = 0; ii < 25; ii++) { a01[ii] = 0ULL; a23[ii] = 0ULL; }
    for (int j = 0; j < NRR; j++) {
        float4 xv = *(const float4*)&Xb[j * IND + c0];
        ull x01, x23;
        asm("mov.b64 %0, {%1,%2};" : "=l"(x01) : "f"(xv.x), "f"(xv.y));
        asm("mov.b64 %0, {%1,%2};" : "=l"(x23) : "f"(xv.z), "f"(xv.w));
#pragma unroll
        for (int ii = 0; ii < 25; ii++) {
            ull s2 = pack2(Ss[(i0 + ii) * NRR + j]);
            a01[ii] = fma2(s2, x01, a01[ii]);
            a23[ii] = fma2(s2, x23, a23[ii]);
        }
    }
#pragma unroll
    for (int ii = 0; ii < 25; ii++) {
        float4 o;
        unpack2(a01[ii], o.x, o.y);
        unpack2(a23[ii], o.z, o.w);
        *(float4*)&out[(b * NRR + i0 + ii) * IND + c0] = o;
    }
}

// ============ launch ============
extern "C" void kernel_launch(void* const* d_in, const int* in_sizes, int n_in,
                              void* d_out, int out_size) {
    const float* Q   = (const float*)d_in[0];
    const float* X   = (const float*)d_in[1];
    const float* Wv  = (const float*)d_in[2];
    const float* bv  = (const float*)d_in[3];
    const float* Wq  = (const float*)d_in[4];
    const float* bq  = (const float*)d_in[5];
    const float* W01 = (const float*)d_in[6];
    const float* b01 = (const float*)d_in[7];
    const float* W02 = (const float*)d_in[8];
    const float* b02 = (const float*)d_in[9];
    const float* W03 = (const float*)d_in[10];
    const float* b03 = (const float*)d_in[11];
    const float* W1  = (const float*)d_in[12];
    const float* b1  = (const float*)d_in[13];
    const float* W2  = (const float*)d_in[14];
    const float* b2  = (const float*)d_in[15];
    const float* W3  = (const float*)d_in[16];
    const float* b3  = (const float*)d_in[17];
    float* out = (float*)d_out;

    cudaFuncSetAttribute(k2_xp, cudaFuncAttributeMaxDynamicSharedMemorySize, K2_SMEM);
    cudaFuncSetAttribute(k3_pair, cudaFuncAttributeMaxDynamicSharedMemorySize, K3_SMEM);

    k0_t<<<592, 256>>>(W01, W1, W02, W2, Wv);
    k1_qp<<<BS, 256>>>(Q, Wq, bq);
    k2_xp<<<dim3(4, 25), 256, K2_SMEM>>>(X, bv);
    k3_pair<<<BS * 49, 256, K3_SMEM>>>(b01, b02, W03, b03, b1, b2, W3, b3);
    k4_softmax<<<BS, 512>>>();
    k5_out<<<dim3(8, BS), 256>>>(X, out);
}

// round 16
// speedup vs baseline: 1.0884x; 1.0305x over previous
#include <cuda_runtime.h>
#include <cuda_bf16.h>
#include <math.h>
#include <stdint.h>

typedef unsigned long long ull;

#define BS 32
#define NRR 100
#define IND 2048
#define QDIM 1024
#define CCH 256

__device__ float g_Qp[BS * CCH];
__device__ float g_Xp[BS * NRR * CCH];
__device__ float g_logits[2 * BS * NRR * NRR];
__device__ float g_S[BS * NRR * NRR];
__device__ __align__(16) unsigned short g_W1h[2 * 128 * 256];
__device__ __align__(16) unsigned short g_W1l[2 * 128 * 256];
__device__ __align__(16) unsigned short g_W2h[2 * 64 * 128];
__device__ __align__(16) unsigned short g_W2l[2 * 64 * 128];
__device__ __align__(16) unsigned short g_Wvh[256 * 2048];
__device__ __align__(16) unsigned short g_Wvl[256 * 2048];

__device__ __forceinline__ ull pack2(float x) {
    ull r; asm("mov.b64 %0, {%1,%1};" : "=l"(r) : "f"(x)); return r;
}
__device__ __forceinline__ ull fma2(ull a, ull b, ull c) {
    ull d; asm("fma.rn.f32x2 %0, %1, %2, %3;" : "=l"(d) : "l"(a), "l"(b), "l"(c)); return d;
}
__device__ __forceinline__ void unpack2(ull v, float& lo, float& hi) {
    asm("mov.b64 {%0,%1}, %2;" : "=f"(lo), "=f"(hi) : "l"(v));
}
__device__ __forceinline__ uint32_t smem_u32(const void* p) {
    uint32_t a;
    asm("{ .reg .u64 t; cvta.to.shared.u64 t, %1; cvt.u32.u64 %0, t; }" : "=r"(a) : "l"(p));
    return a;
}
__device__ __forceinline__ void bsplit(float f0, float f1, uint32_t& hp, uint32_t& lp) {
    asm("cvt.rn.satfinite.bf16x2.f32 %0, %1, %2;" : "=r"(hp) : "f"(f1), "f"(f0));
    float l0 = f0 - __uint_as_float(hp << 16);
    float l1 = f1 - __uint_as_float(hp & 0xFFFF0000u);
    asm("cvt.rn.satfinite.bf16x2.f32 %0, %1, %2;" : "=r"(lp) : "f"(l1), "f"(l0));
}

#define LDSM4(r0, r1, r2, r3, addr) \
    asm volatile("ldmatrix.sync.aligned.m8n8.x4.shared.b16 {%0,%1,%2,%3}, [%4];" \
        : "=r"(r0), "=r"(r1), "=r"(r2), "=r"(r3) : "r"(addr))

#define MMA16816(d, a0, a1, a2, a3, b0, b1) \
    asm volatile("mma.sync.aligned.m16n8k16.row.col.f32.bf16.bf16.f32 " \
        "{%0,%1,%2,%3},{%4,%5,%6,%7},{%8,%9},{%0,%1,%2,%3};" \
        : "+f"((d)[0]), "+f"((d)[1]), "+f"((d)[2]), "+f"((d)[3]) \
        : "r"(a0), "r"(a1), "r"(a2), "r"(a3), "r"(b0), "r"(b1))

#define CPA16(dst, src) \
    asm volatile("cp.async.cg.shared.global [%0], [%1], 16;" :: "r"(dst), "l"(src))
#define CPA_COMMIT() asm volatile("cp.async.commit_group;")
#define CPA_WAIT0() asm volatile("cp.async.wait_group 0;" ::: "memory")
#define CPA_WAIT1() asm volatile("cp.async.wait_group 1;" ::: "memory")

// ============ K0: coalesced tiled transpose + bf16 hi/lo split ============
__global__ __launch_bounds__(256) void k0_t(const float* __restrict__ W01,
                                            const float* __restrict__ W1f,
                                            const float* __restrict__ W02,
                                            const float* __restrict__ W2f,
                                            const float* __restrict__ Wv) {
    __shared__ float s[32][33];
    int t = blockIdx.x;
    const float* src; unsigned short *dh, *dl;
    int K, N, k0, n0;
    if (t < 512) {
        src = Wv; dh = g_Wvh; dl = g_Wvl; K = 2048; N = 256;
        k0 = (t >> 3) * 32; n0 = (t & 7) * 32;
    } else if (t < 576) {
        int u = t - 512; int br = u >> 5; u &= 31;
        src = br ? W1f : W01; dh = g_W1h + br * 32768; dl = g_W1l + br * 32768;
        K = 256; N = 128;
        k0 = (u >> 2) * 32; n0 = (u & 3) * 32;
    } else {
        int u = t - 576; int br = u >> 3; u &= 7;
        src = br ? W2f : W02; dh = g_W2h + br * 8192; dl = g_W2l + br * 8192;
        K = 128; N = 64;
        k0 = (u >> 1) * 32; n0 = (u & 1) * 32;
    }
    int tx = threadIdx.x & 31, ty = threadIdx.x >> 5;
#pragma unroll
    for (int i = ty; i < 32; i += 8)
        s[i][tx] = src[(k0 + i) * N + n0 + tx];
    __syncthreads();
#pragma unroll
    for (int i = ty; i < 32; i += 8) {
        float x = s[tx][i];
        __nv_bfloat16 hb = __float2bfloat16_rn(x);
        __nv_bfloat16 lb = __float2bfloat16_rn(x - __bfloat162float(hb));
        dh[(n0 + i) * K + k0 + tx] = __bfloat16_as_ushort(hb);
        dl[(n0 + i) * K + k0 + tx] = __bfloat16_as_ushort(lb);
    }
}

// ============ K1: Qp = Q @ Wq + bq ============
__global__ void k1_qp(const float* __restrict__ Q, const float* __restrict__ Wq,
                      const float* __restrict__ bq) {
    __shared__ float qs[QDIM];
    int b = blockIdx.x, tid = threadIdx.x;
    for (int k = tid; k < QDIM; k += 256) qs[k] = Q[b * QDIM + k];
    __syncthreads();
    float a0 = 0.f, a1 = 0.f, a2 = 0.f, a3 = 0.f;
    for (int k = 0; k < QDIM; k += 4) {
        a0 += qs[k + 0] * Wq[(k + 0) * CCH + tid];
        a1 += qs[k + 1] * Wq[(k + 1) * CCH + tid];
        a2 += qs[k + 2] * Wq[(k + 2) * CCH + tid];
        a3 += qs[k + 3] * Wq[(k + 3) * CCH + tid];
    }
    g_Qp[b * CCH + tid] = bq[tid] + ((a0 + a1) + (a2 + a3));
}

// ============ K2: Xp = X @ Wv + bv + Qp[b] on mma.sync bf16 3-split (R12-validated) ============
#define K2_XA 0
#define K2_B0 36864
#define K2_B1 55296
#define K2_SMEM 73728

__device__ __forceinline__ void stage_wv(uint32_t base_u, uint32_t bb, int n0, int c, int tid) {
    for (int t = tid; t < 1024; t += 256) {
        int pl = t >> 9, e = t & 511, n = e >> 3, s = e & 7;
        const unsigned short* src = (pl ? g_Wvl : g_Wvh) + (n0 + n) * 2048 + c * 64 + s * 8;
        CPA16(base_u + bb + (uint32_t)pl * 9216u + (uint32_t)(n * 144 + s * 16), src);
    }
    CPA_COMMIT();
}

__global__ __launch_bounds__(256, 1) void k2_xp(const float* __restrict__ X,
                                                const float* __restrict__ bv) {
    extern __shared__ char raw[];
    uint32_t base_u = smem_u32(raw);
    int tid = threadIdx.x, wid = tid >> 5, lane = tid & 31;
    int n0 = blockIdx.x * 64, m0 = blockIdx.y * 128;

    int m0w = wid * 16;
    uint32_t g = lane >> 3, r = lane & 7;
    uint32_t a_row = (uint32_t)(m0w + (int)(g & 1) * 8 + (int)r);
    uint32_t a_k16 = (g >> 1) * 16;
    uint32_t b_row = (g >> 1) * 8 + r;
    uint32_t b_k16 = (g & 1) * 16;

    int mB = tid >> 1, ksB = (tid & 1) * 32;
    const float* xrow = X + (size_t)(m0 + mB) * IND;

    float acc[32];
#pragma unroll
    for (int q = 0; q < 32; q++) acc[q] = 0.f;
    float4 xr[8];

    stage_wv(base_u, K2_B0, n0, 0, tid);
#pragma unroll
    for (int q = 0; q < 8; q++) xr[q] = *(const float4*)(xrow + ksB + q * 4);

    for (int c = 0; c < 32; c++) {
        uint32_t curB = (c & 1) ? K2_B1 : K2_B0;
        uint32_t nxtB = (c & 1) ? K2_B0 : K2_B1;
        bool hn = (c < 31);
        __syncthreads();
        if (hn) stage_wv(base_u, nxtB, n0, c + 1, tid);
        {
            char* ph = raw + K2_XA + mB * 144 + ksB * 2;
            char* pl = ph + 18432;
#pragma unroll
            for (int q = 0; q < 8; q++) {
                uint32_t hp, lp2;
                bsplit(xr[q].x, xr[q].y, hp, lp2);
                *(uint32_t*)(ph + q * 8) = hp;
                *(uint32_t*)(pl + q * 8) = lp2;
                bsplit(xr[q].z, xr[q].w, hp, lp2);
                *(uint32_t*)(ph + q * 8 + 4) = hp;
                *(uint32_t*)(pl + q * 8 + 4) = lp2;
            }
        }
        if (hn) {
#pragma unroll
            for (int q = 0; q < 8; q++)
                xr[q] = *(const float4*)(xrow + (c + 1) * 64 + ksB + q * 4);
            CPA_WAIT1();
        } else {
            CPA_WAIT0();
        }
        __syncthreads();
#pragma unroll
        for (int kf = 0; kf < 4; kf++) {
            uint32_t ah0, ah1, ah2, ah3, al0, al1, al2, al3;
            uint32_t aA = base_u + K2_XA + a_row * 144 + kf * 32 + a_k16;
            LDSM4(ah0, ah1, ah2, ah3, aA);
            LDSM4(al0, al1, al2, al3, aA + 18432);
#pragma unroll
            for (int nf = 0; nf < 4; nf++) {
                uint32_t bh0, bh1, bh2, bh3, bl0, bl1, bl2, bl3;
                uint32_t aB = base_u + curB + (nf * 16 + b_row) * 144 + kf * 32 + b_k16;
                LDSM4(bh0, bh1, bh2, bh3, aB);
                LDSM4(bl0, bl1, bl2, bl3, aB + 9216);
                float* d0 = &acc[nf * 8];
                MMA16816(d0, ah0, ah1, ah2, ah3, bh0, bh1);
                MMA16816(d0, ah0, ah1, ah2, ah3, bl0, bl1);
                MMA16816(d0, al0, al1, al2, al3, bh0, bh1);
                float* d1 = &acc[nf * 8 + 4];
                MMA16816(d1, ah0, ah1, ah2, ah3, bh2, bh3);
                MMA16816(d1, ah0, ah1, ah2, ah3, bl2, bl3);
                MMA16816(d1, al0, al1, al2, al3, bh2, bh3);
            }
        }
    }
    int ln2 = (lane & 3) * 2;
    int row0 = m0 + m0w + (lane >> 2);
    int row1 = row0 + 8;
    int bi0 = row0 / NRR, bi1 = row1 / NRR;
#pragma unroll
    for (int f = 0; f < 8; f++) {
        int n = n0 + f * 8 + ln2;
        float bv0 = bv[n], bv1 = bv[n + 1];
        g_Xp[row0 * CCH + n]     = acc[f * 4 + 0] + bv0 + g_Qp[bi0 * CCH + n];
        g_Xp[row0 * CCH + n + 1] = acc[f * 4 + 1] + bv1 + g_Qp[bi0 * CCH + n + 1];
        g_Xp[row1 * CCH + n]     = acc[f * 4 + 2] + bv0 + g_Qp[bi1 * CCH + n];
        g_Xp[row1 * CCH + n + 1] = acc[f * 4 + 3] + bv1 + g_Qp[bi1 * CCH + n + 1];
    }
}

// ============ K3: pair-MLP — R13 pipeline, GEMM1 warp tile 32Mx64N ============
#define OFF_XI  0
#define OFF_XJ  16640
#define OFF_B1S 24960
#define OFF_B2S 25984
#define OFF_W3S 26496
#define OFF_B3S 27008
#define P0_OFF  27136
#define P1_OFF  64000
#define W0_OFF  100864
#define W1B_OFF 137728
#define H1H_B   27136
#define H1L_B   64000
#define W2H_OFF 100864
#define W2L_OFF 118272
#define K3_SMEM 174592

__device__ __forceinline__ void k3_stage_w1(uint32_t base_u, uint32_t wb, int br, int c, int tid) {
    for (int t = tid; t < 2048; t += 256) {
        int pl = t >> 10, e = t & 1023, n = e >> 3, s = e & 7;
        const unsigned short* src = (pl ? g_W1l : g_W1h) + br * 32768 + n * 256 + c * 64 + s * 8;
        CPA16(base_u + wb + (uint32_t)pl * 18432u + (uint32_t)(n * 144 + s * 16), src);
    }
    CPA_COMMIT();
}
__device__ __forceinline__ void k3_stage_w2(uint32_t base_u, int br, int tid) {
    for (int t = tid; t < 2048; t += 256) {
        int pl = t >> 10, e = t & 1023, n = e >> 4, s = e & 15;
        const unsigned short* src = (pl ? g_W2l : g_W2h) + br * 8192 + n * 128 + s * 8;
        CPA16(base_u + (pl ? W2L_OFF : W2H_OFF) + (uint32_t)(n * 272 + s * 16), src);
    }
    CPA_COMMIT();
}
__device__ __forceinline__ void k3_build_p(char* raw, uint32_t pb, int c,
                                           const float* xir, const float* xjr,
                                           int mB, int ksB) {
    char* ph = raw + pb + mB * 144 + ksB * 2;
    char* pl = ph + 18432;
#pragma unroll
    for (int kk = 0; kk < 32; kk += 2) {
        int k = c * 64 + ksB + kk;
        uint32_t hp, lp;
        bsplit(xir[k] * xjr[k], xir[k + 1] * xjr[k + 1], hp, lp);
        *(uint32_t*)(ph + kk * 2) = hp;
        *(uint32_t*)(pl + kk * 2) = lp;
    }
}
// GEMM1 warp tile: 32M x 64N. mg = wid&3 (rows mg*32+mf*16), ngw = wid>>2 (cols ngw*64).
__device__ __forceinline__ void k3_mma_g1(float* acc1, uint32_t base_u, uint32_t pb, uint32_t wb,
                                          uint32_t a_row1, uint32_t a_k16,
                                          uint32_t b_rowbase, uint32_t b_k16) {
#pragma unroll
    for (int kf = 0; kf < 4; kf++) {
        uint32_t ah[2][4], al[2][4];
#pragma unroll
        for (int mf = 0; mf < 2; mf++) {
            uint32_t aA = base_u + pb + (a_row1 + mf * 16) * 144 + kf * 32 + a_k16;
            LDSM4(ah[mf][0], ah[mf][1], ah[mf][2], ah[mf][3], aA);
            LDSM4(al[mf][0], al[mf][1], al[mf][2], al[mf][3], aA + 18432);
        }
#pragma unroll
        for (int nf = 0; nf < 4; nf++) {
            uint32_t bh0, bh1, bh2, bh3, bl0, bl1, bl2, bl3;
            uint32_t aB = base_u + wb + (b_rowbase + nf * 16) * 144 + kf * 32 + b_k16;
            LDSM4(bh0, bh1, bh2, bh3, aB);
            LDSM4(bl0, bl1, bl2, bl3, aB + 18432);
#pragma unroll
            for (int mf = 0; mf < 2; mf++) {
                float* d0 = &acc1[mf * 32 + nf * 8];
                MMA16816(d0, ah[mf][0], ah[mf][1], ah[mf][2], ah[mf][3], bh0, bh1);
                MMA16816(d0, ah[mf][0], ah[mf][1], ah[mf][2], ah[mf][3], bl0, bl1);
                MMA16816(d0, al[mf][0], al[mf][1], al[mf][2], al[mf][3], bh0, bh1);
                float* d1 = &acc1[mf * 32 + nf * 8 + 4];
                MMA16816(d1, ah[mf][0], ah[mf][1], ah[mf][2], ah[mf][3], bh2, bh3);
                MMA16816(d1, ah[mf][0], ah[mf][1], ah[mf][2], ah[mf][3], bl2, bl3);
                MMA16816(d1, al[mf][0], al[mf][1], al[mf][2], al[mf][3], bh2, bh3);
            }
        }
    }
}

__global__ __launch_bounds__(256, 1) void k3_pair(
    const float* __restrict__ b01, const float* __restrict__ b02,
    const float* __restrict__ W03, const float* __restrict__ b03,
    const float* __restrict__ b1f, const float* __restrict__ b2f,
    const float* __restrict__ W3f, const float* __restrict__ b3f) {
    extern __shared__ char raw[];
    uint32_t base_u = smem_u32(raw);

    int tid = threadIdx.x, wid = tid >> 5, lane = tid & 31;
    int b = blockIdx.x / 49;
    int tile = blockIdx.x % 49;
    int it = 0, u = tile, cnt = 13;
    while (u >= cnt) { u -= cnt; it++; cnt -= 2; }
    int jt = 2 * it + u;
    int i0 = it * 16, j0 = jt * 8;

    float* Xi = (float*)(raw + OFF_XI);
    float* Xj = (float*)(raw + OFF_XJ);
    float* b1s = (float*)(raw + OFF_B1S);
    float* b2s = (float*)(raw + OFF_B2S);
    float* w3s = (float*)(raw + OFF_W3S);
    float* b3s = (float*)(raw + OFF_B3S);

    float4 z = make_float4(0.f, 0.f, 0.f, 0.f);
    for (int t = tid; t < 16 * 64; t += 256) {
        int row = t >> 6, c4 = (t & 63) * 4, gi = i0 + row;
        *(float4*)&Xi[row * 260 + c4] =
            (gi < NRR) ? *(const float4*)&g_Xp[(b * NRR + gi) * CCH + c4] : z;
    }
    for (int t = tid; t < 8 * 64; t += 256) {
        int row = t >> 6, c4 = (t & 63) * 4, gj = j0 + row;
        *(float4*)&Xj[row * 260 + c4] =
            (gj < NRR) ? *(const float4*)&g_Xp[(b * NRR + gj) * CCH + c4] : z;
    }
    if (tid < 128) { b1s[tid] = b01[tid]; b1s[128 + tid] = b1f[tid]; }
    if (tid < 64) {
        b2s[tid] = b02[tid]; b2s[64 + tid] = b2f[tid];
        w3s[tid] = W03[tid]; w3s[64 + tid] = W3f[tid];
    }
    if (tid == 0) { b3s[0] = b03[0]; b3s[1] = b3f[0]; }
    __syncthreads();

    int m0w = wid * 16;                 // GEMM2/GEMM3 mapping (unchanged)
    int mg = wid & 3, ngw = wid >> 2;   // GEMM1 warp tile mapping
    uint32_t g = lane >> 3, r = lane & 7;
    uint32_t a_row = (uint32_t)(m0w + (int)(g & 1) * 8 + (int)r);
    uint32_t a_row1 = (uint32_t)(mg * 32 + (int)(g & 1) * 8 + (int)r);
    uint32_t a_k16 = (g >> 1) * 16;
    uint32_t b_row = (g >> 1) * 8 + r;
    uint32_t b_rowbase = (uint32_t)(ngw * 64) + b_row;
    uint32_t b_k16 = (g & 1) * 16;

    int mB = tid >> 1, ksB = (tid & 1) * 32;
    const float* xir = Xi + (mB >> 3) * 260;
    const float* xjr = Xj + (mB & 7) * 260;
    int ln2 = (lane & 3) * 2;

    for (int br = 0; br < 2; br++) {
        float acc1[64];
#pragma unroll
        for (int q = 0; q < 64; q++) acc1[q] = 0.f;

        k3_stage_w1(base_u, W0_OFF, br, 0, tid);
        k3_build_p(raw, P0_OFF, 0, xir, xjr, mB, ksB);
        CPA_WAIT0();
        __syncthreads();

#pragma unroll
        for (int c = 0; c < 4; c++) {
            uint32_t pCur = (c & 1) ? P1_OFF : P0_OFF;
            uint32_t wCur = (c & 1) ? W1B_OFF : W0_OFF;
            uint32_t pNxt = (c & 1) ? P0_OFF : P1_OFF;
            uint32_t wNxt = (c & 1) ? W0_OFF : W1B_OFF;
            if (c < 3) {
                k3_stage_w1(base_u, wNxt, br, c + 1, tid);
                k3_build_p(raw, pNxt, c + 1, xir, xjr, mB, ksB);
            } else {
                k3_stage_w2(base_u, br, tid);
            }
            k3_mma_g1(acc1, base_u, pCur, wCur, a_row1, a_k16, b_rowbase, b_k16);
            CPA_WAIT0();
            __syncthreads();
        }

        // H1 epilogue (32Mx64N fragment mapping -> same chunked smem planes)
        {
            int rowBase = mg * 32 + (lane >> 2);
#pragma unroll
            for (int mf = 0; mf < 2; mf++) {
                int rowA = rowBase + mf * 16;
#pragma unroll
                for (int nf = 0; nf < 4; nf++) {
#pragma unroll
                    for (int half = 0; half < 2; half++) {
                        int n = ngw * 64 + nf * 16 + half * 8 + ln2;
                        int ch = n >> 6, nin = n & 63;
                        char* hh = raw + H1H_B + ch * 18432 + nin * 2;
                        char* hl = raw + H1L_B + ch * 18432 + nin * 2;
                        const float* a4 = &acc1[mf * 32 + nf * 8 + half * 4];
                        float c0v = b1s[br * 128 + n], c1v = b1s[br * 128 + n + 1];
                        uint32_t hp, lp;
                        bsplit(fmaxf(a4[0] + c0v, 0.f), fmaxf(a4[1] + c1v, 0.f), hp, lp);
                        *(uint32_t*)(hh + rowA * 144) = hp;
                        *(uint32_t*)(hl + rowA * 144) = lp;
                        bsplit(fmaxf(a4[2] + c0v, 0.f), fmaxf(a4[3] + c1v, 0.f), hp, lp);
                        *(uint32_t*)(hh + (rowA + 8) * 144) = hp;
                        *(uint32_t*)(hl + (rowA + 8) * 144) = lp;
                    }
                }
            }
        }
        __syncthreads();

        float acc2[32];
#pragma unroll
        for (int q = 0; q < 32; q++) acc2[q] = 0.f;
#pragma unroll
        for (int kf = 0; kf < 8; kf++) {
            int ch = kf >> 2, kfin = kf & 3;
            uint32_t ah0, ah1, ah2, ah3, al0, al1, al2, al3;
            uint32_t aAh = base_u + H1H_B + ch * 18432 + a_row * 144 + kfin * 32 + a_k16;
            uint32_t aAl = base_u + H1L_B + ch * 18432 + a_row * 144 + kfin * 32 + a_k16;
            LDSM4(ah0, ah1, ah2, ah3, aAh);
            LDSM4(al0, al1, al2, al3, aAl);
#pragma unroll
            for (int nf = 0; nf < 4; nf++) {
                uint32_t bh0, bh1, bh2, bh3, bl0, bl1, bl2, bl3;
                uint32_t aB = base_u + W2H_OFF + (nf * 16 + b_row) * 272 + kf * 32 + b_k16;
                LDSM4(bh0, bh1, bh2, bh3, aB);
                LDSM4(bl0, bl1, bl2, bl3, aB + 17408);
                float* d0 = &acc2[nf * 8];
                MMA16816(d0, ah0, ah1, ah2, ah3, bh0, bh1);
                MMA16816(d0, ah0, ah1, ah2, ah3, bl0, bl1);
                MMA16816(d0, al0, al1, al2, al3, bh0, bh1);
                float* d1 = &acc2[nf * 8 + 4];
                MMA16816(d1, ah0, ah1, ah2, ah3, bh2, bh3);
                MMA16816(d1, ah0, ah1, ah2, ah3, bl2, bl3);
                MMA16816(d1, al0, al1, al2, al3, bh2, bh3);
            }
        }

        {
            float p0 = 0.f, p1 = 0.f;
#pragma unroll
            for (int f = 0; f < 8; f++) {
                int n = f * 8 + ln2;
                float w0 = w3s[br * 64 + n], w1 = w3s[br * 64 + n + 1];
                float c0 = b2s[br * 64 + n], c1 = b2s[br * 64 + n + 1];
                p0 += fmaxf(acc2[f * 4 + 0] + c0, 0.f) * w0
                    + fmaxf(acc2[f * 4 + 1] + c1, 0.f) * w1;
                p1 += fmaxf(acc2[f * 4 + 2] + c0, 0.f) * w0
                    + fmaxf(acc2[f * 4 + 3] + c1, 0.f) * w1;
            }
            p0 += __shfl_xor_sync(~0u, p0, 1); p0 += __shfl_xor_sync(~0u, p0, 2);
            p1 += __shfl_xor_sync(~0u, p1, 1); p1 += __shfl_xor_sync(~0u, p1, 2);
            if ((lane & 3) == 0) {
                int q = lane >> 2;
                float* L = g_logits + (br * BS + b) * (NRR * NRR);
                int m1 = m0w + q, m2 = m0w + q + 8;
                float v0 = 2.f * fmaxf(p0 + b3s[br], 0.f);
                float v1 = 2.f * fmaxf(p1 + b3s[br], 0.f);
                int i1 = i0 + (m1 >> 3), j1 = j0 + (m1 & 7);
                int i2 = i0 + (m2 >> 3), j2 = j0 + (m2 & 7);
                if (i1 < NRR && j1 < NRR) { L[i1 * NRR + j1] = v0; L[j1 * NRR + i1] = v0; }
                if (i2 < NRR && j2 < NRR) { L[i2 * NRR + j2] = v1; L[j2 * NRR + i2] = v1; }
            }
        }
        __syncthreads();
    }
}

// ============ K4: softmax per (b,branch) + combine ============
__global__ __launch_bounds__(512) void k4_softmax() {
    int b = blockIdx.x, tid = threadIdx.x;
    __shared__ float red[16];
    __shared__ float bm[2], bsum[2];
    const int NE = NRR * NRR;
    for (int br = 0; br < 2; br++) {
        const float* L = g_logits + (br * BS + b) * NE;
        float m = -1e30f;
        for (int e = tid; e < NE; e += 512) m = fmaxf(m, L[e]);
        for (int o = 16; o; o >>= 1) m = fmaxf(m, __shfl_xor_sync(~0u, m, o));
        if ((tid & 31) == 0) red[tid >> 5] = m;
        __syncthreads();
        if (tid == 0) {
            float a = red[0];
            for (int w = 1; w < 16; w++) a = fmaxf(a, red[w]);
            bm[br] = a;
        }
        __syncthreads();
        float mm = bm[br], s = 0.f;
        for (int e = tid; e < NE; e += 512) s += __expf(L[e] - mm);
        for (int o = 16; o; o >>= 1) s += __shfl_xor_sync(~0u, s, o);
        if ((tid & 31) == 0) red[tid >> 5] = s;
        __syncthreads();
        if (tid == 0) {
            float a = red[0];
            for (int w = 1; w < 16; w++) a += red[w];
            bsum[br] = a;
        }
        __syncthreads();
    }
    float m0 = bm[0], is0 = 1.f / bsum[0];
    float m1 = bm[1], is1 = 1.f / bsum[1];
    const float* L0 = g_logits + b * NE;
    const float* L1 = g_logits + (BS + b) * NE;
    float* S = g_S + b * NE;
    for (int e = tid; e < NE; e += 512)
        S[e] = 0.5f * (__expf(L0[e] - m0) * is0 + __expf(L1[e] - m1) * is1);
}

// ============ K5: out = S @ X (f32x2, row split) ============
__global__ __launch_bounds__(256) void k5_out(const float* __restrict__ X,
                                              float* __restrict__ out) {
    __shared__ float Ss[NRR * NRR];
    int b = blockIdx.y, tid = threadIdx.x;
    for (int e = tid; e < NRR * NRR; e += 256) Ss[e] = g_S[b * NRR * NRR + e];
    __syncthreads();
    int tx = tid & 63, ty = tid >> 6;
    int c0 = blockIdx.x * 256 + tx * 4;
    int i0 = ty * 25;
    const float* Xb = X + b * NRR * IND;
    ull a01[25], a23[25];
#pragma unroll
    for (int ii = 0; ii < 25; ii++) { a01[ii] = 0ULL; a23[ii] = 0ULL; }
    for (int j = 0; j < NRR; j++) {
        float4 xv = *(const float4*)&Xb[j * IND + c0];
        ull x01, x23;
        asm("mov.b64 %0, {%1,%2};" : "=l"(x01) : "f"(xv.x), "f"(xv.y));
        asm("mov.b64 %0, {%1,%2};" : "=l"(x23) : "f"(xv.z), "f"(xv.w));
#pragma unroll
        for (int ii = 0; ii < 25; ii++) {
            ull s2 = pack2(Ss[(i0 + ii) * NRR + j]);
            a01[ii] = fma2(s2, x01, a01[ii]);
            a23[ii] = fma2(s2, x23, a23[ii]);
        }
    }
#pragma unroll
    for (int ii = 0; ii < 25; ii++) {
        float4 o;
        unpack2(a01[ii], o.x, o.y);
        unpack2(a23[ii], o.z, o.w);
        *(float4*)&out[(b * NRR + i0 + ii) * IND + c0] = o;
    }
}

// ============ launch ============
extern "C" void kernel_launch(void* const* d_in, const int* in_sizes, int n_in,
                              void* d_out, int out_size) {
    const float* Q   = (const float*)d_in[0];
    const float* X   = (const float*)d_in[1];
    const float* Wv  = (const float*)d_in[2];
    const float* bv  = (const float*)d_in[3];
    const float* Wq  = (const float*)d_in[4];
    const float* bq  = (const float*)d_in[5];
    const float* W01 = (const float*)d_in[6];
    const float* b01 = (const float*)d_in[7];
    const float* W02 = (const float*)d_in[8];
    const float* b02 = (const float*)d_in[9];
    const float* W03 = (const float*)d_in[10];
    const float* b03 = (const float*)d_in[11];
    const float* W1  = (const float*)d_in[12];
    const float* b1  = (const float*)d_in[13];
    const float* W2  = (const float*)d_in[14];
    const float* b2  = (const float*)d_in[15];
    const float* W3  = (const float*)d_in[16];
    const float* b3  = (const float*)d_in[17];
    float* out = (float*)d_out;

    cudaFuncSetAttribute(k2_xp, cudaFuncAttributeMaxDynamicSharedMemorySize, K2_SMEM);
    cudaFuncSetAttribute(k3_pair, cudaFuncAttributeMaxDynamicSharedMemorySize, K3_SMEM);

    k0_t<<<592, 256>>>(W01, W1, W02, W2, Wv);
    k1_qp<<<BS, 256>>>(Q, Wq, bq);
    k2_xp<<<dim3(4, 25), 256, K2_SMEM>>>(X, bv);
    k3_pair<<<BS * 49, 256, K3_SMEM>>>(b01, b02, W03, b03, b1, b2, W3, b3);
    k4_softmax<<<BS, 512>>>();
    k5_out<<<dim3(8, BS), 256>>>(X, out);
}